// round 1
// baseline (speedup 1.0000x reference)
#include <cuda_runtime.h>

#define M_ 4
#define B_ 2048
#define D_ 1024
#define O_ 1024
#define E_ 8
#define C_ 2

// Folded per-expert head: g_fold_w[e][d][c] = sum_o expert_w[e][d][o] * head_w[o][c]
// g_fold_b[e][c] = sum_o expert_b[e][o] * head_w[o][c]
__device__ float g_fold_w[E_ * D_ * C_];   // 64 KB
__device__ float g_fold_b[E_ * C_];

// ---------------------------------------------------------------------------
// Kernel A: fold expert_w (and expert_b) through head_w.
// One warp per row r = e*D + d (rows are contiguous: row base = r*O).
// blockIdx.x in [0, E*D/8): weight rows; blockIdx.x == E*D/8: bias rows.
// ---------------------------------------------------------------------------
__global__ __launch_bounds__(256) void fold_kernel(
    const float* __restrict__ expert_w,
    const float* __restrict__ expert_b,
    const float* __restrict__ head_w) {
  __shared__ float4 sh[O_ * C_ / 4];  // head_w staged: 2048 floats = 8 KB
  for (int t = threadIdx.x; t < O_ * C_ / 4; t += 256)
    sh[t] = reinterpret_cast<const float4*>(head_w)[t];
  __syncthreads();

  const int warp = threadIdx.x >> 5;
  const int lane = threadIdx.x & 31;
  const bool is_bias = (blockIdx.x == (E_ * D_ / 8));
  int r;
  const float4* src;
  if (!is_bias) {
    r = blockIdx.x * 8 + warp;                                   // [0, E*D)
    src = reinterpret_cast<const float4*>(expert_w) + (size_t)r * (O_ / 4);
  } else {
    r = warp;                                                    // expert id
    src = reinterpret_cast<const float4*>(expert_b) + (size_t)r * (O_ / 4);
  }

  float a0 = 0.f, a1 = 0.f;
#pragma unroll
  for (int i = 0; i < 8; i++) {
    int o = i * 128 + lane * 4;
    float4 w  = src[o >> 2];
    float4 h0 = sh[o >> 1];
    float4 h1 = sh[(o >> 1) + 1];
    a0 += w.x * h0.x + w.y * h0.z + w.z * h1.x + w.w * h1.z;
    a1 += w.x * h0.y + w.y * h0.w + w.z * h1.y + w.w * h1.w;
  }
#pragma unroll
  for (int off = 16; off; off >>= 1) {
    a0 += __shfl_xor_sync(0xffffffffu, a0, off);
    a1 += __shfl_xor_sync(0xffffffffu, a1, off);
  }
  if (lane == 0) {
    if (!is_bias)
      reinterpret_cast<float2*>(g_fold_w)[r] = make_float2(a0, a1);
    else
      reinterpret_cast<float2*>(g_fold_b)[r] = make_float2(a0, a1);
  }
}

// ---------------------------------------------------------------------------
// Kernel B: per-token gating + routed folded-expert dot + mean over M + head_b.
// One block per b (2048 blocks), one warp per modality m (4 warps).
// ---------------------------------------------------------------------------
__global__ __launch_bounds__(128) void moe_kernel(
    const float* __restrict__ x,
    const float* __restrict__ gate_w,
    const float* __restrict__ gate_b,
    const float* __restrict__ head_b,
    float* __restrict__ out) {
  const int b = blockIdx.x;
  const int m = threadIdx.x >> 5;
  const int lane = threadIdx.x & 31;
  __shared__ float red[M_][C_];

  const float* xr = x + ((size_t)m * B_ + b) * D_;

  float xv[32];
  float acc[E_];
#pragma unroll
  for (int e = 0; e < E_; e++) acc[e] = 0.f;

  // Gate logits: lane owns d = i*32 + lane. x loads coalesced (128B/warp),
  // gate_w loads 1KB-contiguous per warp-iter, L1-resident after warmup.
#pragma unroll
  for (int i = 0; i < 32; i++) {
    int d = i * 32 + lane;
    float xd = xr[d];
    xv[i] = xd;
    const float4* g4 = reinterpret_cast<const float4*>(gate_w + d * E_);
    float4 g0 = g4[0], g1 = g4[1];
    acc[0] += xd * g0.x; acc[1] += xd * g0.y;
    acc[2] += xd * g0.z; acc[3] += xd * g0.w;
    acc[4] += xd * g1.x; acc[5] += xd * g1.y;
    acc[6] += xd * g1.z; acc[7] += xd * g1.w;
  }
#pragma unroll
  for (int e = 0; e < E_; e++) {
#pragma unroll
    for (int off = 16; off; off >>= 1)
      acc[e] += __shfl_xor_sync(0xffffffffu, acc[e], off);
    acc[e] += gate_b[e];
  }

  // winner = max index among the two largest logits (ties -> lower index
  // first, matching jax.lax.top_k stability).
  int i1 = 0; float v1 = acc[0];
#pragma unroll
  for (int e = 1; e < E_; e++) if (acc[e] > v1) { v1 = acc[e]; i1 = e; }
  int i2 = 0; float v2 = -3.402823466e38f;
#pragma unroll
  for (int e = 0; e < E_; e++)
    if (e != i1 && acc[e] > v2) { v2 = acc[e]; i2 = e; }
  const int winner = (i1 > i2) ? i1 : i2;

  // Routed folded dot: y[c] = sum_d x[d] * fold_w[winner][d][c]
  const float2* fw = reinterpret_cast<const float2*>(g_fold_w) + winner * D_;
  float y0 = 0.f, y1 = 0.f;
#pragma unroll
  for (int i = 0; i < 32; i++) {
    float2 f = fw[i * 32 + lane];
    y0 += xv[i] * f.x;
    y1 += xv[i] * f.y;
  }
#pragma unroll
  for (int off = 16; off; off >>= 1) {
    y0 += __shfl_xor_sync(0xffffffffu, y0, off);
    y1 += __shfl_xor_sync(0xffffffffu, y1, off);
  }

  if (lane == 0) {
    red[m][0] = y0 + g_fold_b[winner * C_ + 0];
    red[m][1] = y1 + g_fold_b[winner * C_ + 1];
  }
  __syncthreads();
  if (threadIdx.x < C_) {
    float s = red[0][threadIdx.x] + red[1][threadIdx.x] +
              red[2][threadIdx.x] + red[3][threadIdx.x];
    out[b * C_ + threadIdx.x] = 0.25f * s + head_b[threadIdx.x];
  }
}

// ---------------------------------------------------------------------------
// Inputs (metadata order): x, gate_w, gate_b, expert_w, expert_b, head_w, head_b
// ---------------------------------------------------------------------------
extern "C" void kernel_launch(void* const* d_in, const int* in_sizes, int n_in,
                              void* d_out, int out_size) {
  const float* x        = (const float*)d_in[0];
  const float* gate_w   = (const float*)d_in[1];
  const float* gate_b   = (const float*)d_in[2];
  const float* expert_w = (const float*)d_in[3];
  const float* expert_b = (const float*)d_in[4];
  const float* head_w   = (const float*)d_in[5];
  const float* head_b   = (const float*)d_in[6];
  float* out = (float*)d_out;

  fold_kernel<<<E_ * D_ / 8 + 1, 256>>>(expert_w, expert_b, head_w);
  moe_kernel<<<B_, 128>>>(x, gate_w, gate_b, head_b, out);
}

// round 2
// speedup vs baseline: 1.1097x; 1.1097x over previous
#include <cuda_runtime.h>

#define M_ 4
#define B_ 2048
#define D_ 1024
#define O_ 1024
#define E_ 8
#define C_ 2

// Folded per-expert head: g_fold_w[e][d][c] = sum_o expert_w[e][d][o] * head_w[o][c]
__device__ float g_fold_w[E_ * D_ * C_];   // 64 KB
__device__ float g_fold_b[E_ * C_];
__device__ float g_gate_t[E_ * D_];        // transposed gate: [E][D], 32 KB

__device__ __forceinline__ float wsum(float v) {
#pragma unroll
  for (int o = 16; o; o >>= 1) v += __shfl_xor_sync(0xffffffffu, v, o);
  return v;
}

// ---------------------------------------------------------------------------
// Kernel A: fold expert_w / expert_b through head_w; transpose gate_w.
// bid < 512           : weight rows, 2 rows per warp (16 rows/block)
// bid == 512          : bias rows, 1 expert per warp
// bid == 513          : gate transpose
// ---------------------------------------------------------------------------
__global__ __launch_bounds__(256) void fold_kernel(
    const float* __restrict__ expert_w,
    const float* __restrict__ expert_b,
    const float* __restrict__ gate_w,
    const float* __restrict__ head_w) {
  const int bid = blockIdx.x;
  if (bid == 513) {  // transpose gate_w [D,E] -> g_gate_t [E,D] (32KB, cheap)
    for (int t = threadIdx.x; t < E_ * D_; t += 256) {
      int d = t >> 3, e = t & 7;
      g_gate_t[e * D_ + d] = gate_w[t];
    }
    return;
  }
  __shared__ float4 sh[O_ * C_ / 4];  // head_w staged: 8 KB
  for (int t = threadIdx.x; t < O_ * C_ / 4; t += 256)
    sh[t] = reinterpret_cast<const float4*>(head_w)[t];
  __syncthreads();

  const int warp = threadIdx.x >> 5;
  const int lane = threadIdx.x & 31;

  if (bid < 512) {
    const int r0 = bid * 16 + warp * 2;
    const float4* s0 = reinterpret_cast<const float4*>(expert_w) + (size_t)r0 * (O_ / 4);
    const float4* s1 = s0 + (O_ / 4);
    float a00 = 0.f, a01 = 0.f, a10 = 0.f, a11 = 0.f;
#pragma unroll
    for (int i = 0; i < 8; i++) {
      int o = i * 128 + lane * 4;
      float4 w0 = s0[o >> 2], w1 = s1[o >> 2];
      float4 h0 = sh[o >> 1], h1 = sh[(o >> 1) + 1];
      a00 += w0.x * h0.x + w0.y * h0.z + w0.z * h1.x + w0.w * h1.z;
      a01 += w0.x * h0.y + w0.y * h0.w + w0.z * h1.y + w0.w * h1.w;
      a10 += w1.x * h0.x + w1.y * h0.z + w1.z * h1.x + w1.w * h1.z;
      a11 += w1.x * h0.y + w1.y * h0.w + w1.z * h1.y + w1.w * h1.w;
    }
    a00 = wsum(a00); a01 = wsum(a01); a10 = wsum(a10); a11 = wsum(a11);
    if (lane == 0) {
      reinterpret_cast<float2*>(g_fold_w)[r0]     = make_float2(a00, a01);
      reinterpret_cast<float2*>(g_fold_w)[r0 + 1] = make_float2(a10, a11);
    }
  } else if (warp < E_) {  // bid == 512: bias fold
    const float4* s = reinterpret_cast<const float4*>(expert_b) + warp * (O_ / 4);
    float a0 = 0.f, a1 = 0.f;
#pragma unroll
    for (int i = 0; i < 8; i++) {
      int o = i * 128 + lane * 4;
      float4 w = s[o >> 2];
      float4 h0 = sh[o >> 1], h1 = sh[(o >> 1) + 1];
      a0 += w.x * h0.x + w.y * h0.z + w.z * h1.x + w.w * h1.z;
      a1 += w.x * h0.y + w.y * h0.w + w.z * h1.y + w.w * h1.w;
    }
    a0 = wsum(a0); a1 = wsum(a1);
    if (lane == 0)
      reinterpret_cast<float2*>(g_fold_b)[warp] = make_float2(a0, a1);
  }
}

// ---------------------------------------------------------------------------
// Kernel B: each warp handles 8 token-instances = (4 modalities x 2 batch
// columns). Gate weights amortized 8x; all loads LDG.128 coalesced.
// ---------------------------------------------------------------------------
__global__ __launch_bounds__(64) void moe_kernel(
    const float* __restrict__ x,
    const float* __restrict__ gate_b,
    const float* __restrict__ head_b,
    float* __restrict__ out) {
  const int wid  = blockIdx.x * 2 + (threadIdx.x >> 5);  // global warp id
  const int lane = threadIdx.x & 31;
  const int b0   = wid * 2;

  const float4* x4     = reinterpret_cast<const float4*>(x);
  const float4* gate4  = reinterpret_cast<const float4*>(g_gate_t);
  const float4* fold4  = reinterpret_cast<const float4*>(g_fold_w);

  // Phase 1: gate logits for 8 instances. acc[inst][e]
  float acc[8][8];
#pragma unroll
  for (int i = 0; i < 8; i++)
#pragma unroll
    for (int e = 0; e < E_; e++) acc[i][e] = 0.f;

#pragma unroll
  for (int ch = 0; ch < 8; ch++) {
    float4 xr[8];
#pragma unroll
    for (int inst = 0; inst < 8; inst++) {
      int m = inst >> 1, tb = inst & 1;
      xr[inst] = x4[(m * B_ + b0 + tb) * (D_ / 4) + ch * 32 + lane];
    }
#pragma unroll
    for (int e = 0; e < E_; e++) {
      float4 g = gate4[e * (D_ / 4) + ch * 32 + lane];
#pragma unroll
      for (int inst = 0; inst < 8; inst++)
        acc[inst][e] += xr[inst].x * g.x + xr[inst].y * g.y +
                        xr[inst].z * g.z + xr[inst].w * g.w;
    }
  }

  // Phase 2: per instance — reduce logits, pick winner, routed folded dot.
  float s00 = 0.f, s01 = 0.f, s10 = 0.f, s11 = 0.f;  // [tb][c]
#pragma unroll
  for (int inst = 0; inst < 8; inst++) {
    const int m = inst >> 1, tb = inst & 1;
    float l[8];
#pragma unroll
    for (int e = 0; e < E_; e++) l[e] = wsum(acc[inst][e]) + gate_b[e];

    // winner = max index among two largest logits (top_k stability: ties
    // resolve to lower index first).
    int i1 = 0; float v1 = l[0];
#pragma unroll
    for (int e = 1; e < E_; e++) if (l[e] > v1) { v1 = l[e]; i1 = e; }
    int i2 = 0; float v2 = -3.402823466e38f;
#pragma unroll
    for (int e = 0; e < E_; e++)
      if (e != i1 && l[e] > v2) { v2 = l[e]; i2 = e; }
    const int winner = (i1 > i2) ? i1 : i2;

    const float4* fw  = fold4 + winner * (D_ * C_ / 4);
    const float4* xr4 = x4 + (m * B_ + b0 + tb) * (D_ / 4);
    float y0 = 0.f, y1 = 0.f;
#pragma unroll
    for (int ch = 0; ch < 8; ch++) {
      float4 xr = xr4[ch * 32 + lane];                 // reload: L1/L2 hit
      float4 f0 = fw[ch * 64 + lane * 2];
      float4 f1 = fw[ch * 64 + lane * 2 + 1];
      y0 += xr.x * f0.x + xr.y * f0.z + xr.z * f1.x + xr.w * f1.z;
      y1 += xr.x * f0.y + xr.y * f0.w + xr.z * f1.y + xr.w * f1.w;
    }
    y0 = wsum(y0) + g_fold_b[winner * C_ + 0];
    y1 = wsum(y1) + g_fold_b[winner * C_ + 1];
    if (tb == 0) { s00 += y0; s01 += y1; }
    else         { s10 += y0; s11 += y1; }
  }

  if (lane == 0)
    reinterpret_cast<float2*>(out)[b0] =
        make_float2(0.25f * s00 + head_b[0], 0.25f * s01 + head_b[1]);
  if (lane == 1)
    reinterpret_cast<float2*>(out)[b0 + 1] =
        make_float2(0.25f * s10 + head_b[0], 0.25f * s11 + head_b[1]);
}

// ---------------------------------------------------------------------------
// Inputs (metadata order): x, gate_w, gate_b, expert_w, expert_b, head_w, head_b
// ---------------------------------------------------------------------------
extern "C" void kernel_launch(void* const* d_in, const int* in_sizes, int n_in,
                              void* d_out, int out_size) {
  const float* x        = (const float*)d_in[0];
  const float* gate_w   = (const float*)d_in[1];
  const float* gate_b   = (const float*)d_in[2];
  const float* expert_w = (const float*)d_in[3];
  const float* expert_b = (const float*)d_in[4];
  const float* head_w   = (const float*)d_in[5];
  const float* head_b   = (const float*)d_in[6];
  float* out = (float*)d_out;

  fold_kernel<<<514, 256>>>(expert_w, expert_b, gate_w, head_w);
  moe_kernel<<<B_ / 4, 64>>>(x, gate_b, head_b, out);
}